// round 2
// baseline (speedup 1.0000x reference)
#include <cuda_runtime.h>
#include <cstdint>
#include <math.h>

#define BCAP 262144
#define HSTR 260        // H smem row stride (floats): %32==4 -> conflict-free A frags
#define WSTR 264        // W smem row stride (floats): %32==8 -> conflict-free B frags
#define SMEM_FLOATS (128*HSTR + 2*32*WSTR + 256)
#define SMEM_BYTES  (SMEM_FLOATS*4)

__device__ float g_feats[(size_t)BCAP*32];
__device__ float g_R[(size_t)BCAP*9];
__device__ float g_b1eff[256];

// ---------------- helpers ----------------
__device__ __forceinline__ uint32_t f2tf(float v){
  uint32_t r; asm("cvt.rna.tf32.f32 %0, %1;" : "=r"(r) : "f"(v)); return r;
}
__device__ __forceinline__ void split2(float v, uint32_t &h, uint32_t &l){
  h = f2tf(v);
  l = f2tf(v - __uint_as_float(h));
}
__device__ __forceinline__ void mma8(float d[4], uint32_t a0,uint32_t a1,uint32_t a2,uint32_t a3,
                                     uint32_t b0, uint32_t b1){
  asm volatile("mma.sync.aligned.m16n8k8.row.col.f32.tf32.tf32.f32 "
               "{%0,%1,%2,%3},{%4,%5,%6,%7},{%8,%9},{%0,%1,%2,%3};\n"
               : "+f"(d[0]),"+f"(d[1]),"+f"(d[2]),"+f"(d[3])
               : "r"(a0),"r"(a1),"r"(a2),"r"(a3),"r"(b0),"r"(b1));
}
__device__ __forceinline__ float gelu_f(float x){
  return 0.5f*x*(1.0f + erff(x*0.7071067811865476f));
}
__device__ __forceinline__ void cpa16(uint32_t dst, const void* src){
  asm volatile("cp.async.cg.shared.global [%0], [%1], 16;\n" :: "r"(dst), "l"(src) : "memory");
}
__device__ __forceinline__ void cpa_commit(){ asm volatile("cp.async.commit_group;\n" ::: "memory"); }

// ---------------- phase 1: per-element features (polar + eigen) ----------------
__global__ void prep_kernel(const float* __restrict__ F, const float* __restrict__ C, int B){
  int i = blockIdx.x*blockDim.x + threadIdx.x;
  if (i >= B) return;
  float f[9];
#pragma unroll
  for (int k=0;k<9;k++) f[k] = F[(size_t)i*9+k];

  // Higham polar iteration: X <- 0.5*(X + X^{-T});  X^{-T} = cof(X)/det(X)
  float x[9];
#pragma unroll
  for (int k=0;k<9;k++) x[k]=f[k];
#pragma unroll
  for (int it=0; it<5; it++){
    float c00 = x[4]*x[8]-x[5]*x[7];
    float c01 = x[5]*x[6]-x[3]*x[8];
    float c02 = x[3]*x[7]-x[4]*x[6];
    float c10 = x[2]*x[7]-x[1]*x[8];
    float c11 = x[0]*x[8]-x[2]*x[6];
    float c12 = x[1]*x[6]-x[0]*x[7];
    float c20 = x[1]*x[5]-x[2]*x[4];
    float c21 = x[2]*x[3]-x[0]*x[5];
    float c22 = x[0]*x[4]-x[1]*x[3];
    float det = x[0]*c00 + x[1]*c01 + x[2]*c02;
    float s = 0.5f/det;
    x[0]=0.5f*x[0]+s*c00; x[1]=0.5f*x[1]+s*c01; x[2]=0.5f*x[2]+s*c02;
    x[3]=0.5f*x[3]+s*c10; x[4]=0.5f*x[4]+s*c11; x[5]=0.5f*x[5]+s*c12;
    x[6]=0.5f*x[6]+s*c20; x[7]=0.5f*x[7]+s*c21; x[8]=0.5f*x[8]+s*c22;
  }

  // S = F^T F  (S[i][j] = sum_r f[3r+i]*f[3r+j])
  float s00 = f[0]*f[0]+f[3]*f[3]+f[6]*f[6];
  float s11 = f[1]*f[1]+f[4]*f[4]+f[7]*f[7];
  float s22 = f[2]*f[2]+f[5]*f[5]+f[8]*f[8];
  float s01 = f[0]*f[1]+f[3]*f[4]+f[6]*f[7];
  float s02 = f[0]*f[2]+f[3]*f[5]+f[6]*f[8];
  float s12 = f[1]*f[2]+f[4]*f[5]+f[7]*f[8];

  // closed-form eigenvalues of symmetric S, descending
  float q  = (s00+s11+s22)*(1.0f/3.0f);
  float b00=s00-q, b11=s11-q, b22=s22-q;
  float p2 = (b00*b00+b11*b11+b22*b22 + 2.0f*(s01*s01+s02*s02+s12*s12))*(1.0f/6.0f);
  float p  = sqrtf(fmaxf(p2, 0.0f));
  float l1,l2,l3;
  if (p < 1e-10f){ l1=l2=l3=q; }
  else {
    float detB = b00*(b11*b22 - s12*s12) - s01*(s01*b22 - s12*s02) + s02*(s01*s12 - b11*s02);
    float r = detB/(2.0f*p*p*p);
    r = fminf(1.0f, fmaxf(-1.0f, r));
    float phi = acosf(r)*(1.0f/3.0f);
    l1 = q + 2.0f*p*cosf(phi);
    l3 = q + 2.0f*p*cosf(phi + 2.0943951023931953f);
    l2 = 3.0f*q - l1 - l3;
  }
  float sg1 = sqrtf(fmaxf(l1,0.0f));
  float sg2 = sqrtf(fmaxf(l2,0.0f));
  float sg3 = sqrtf(fmaxf(l3,0.0f));

  float detF = f[0]*(f[4]*f[8]-f[5]*f[7]) - f[1]*(f[3]*f[8]-f[5]*f[6]) + f[2]*(f[3]*f[7]-f[4]*f[6]);
  float ld   = logf(detF);
  float f00c = fmaxf(f[0], 1e-6f);

  float* ft = g_feats + (size_t)i*32;
  ft[0]=sg1-1.0f; ft[1]=sg2-1.0f; ft[2]=sg3-1.0f;
  ft[3]=s00-1.0f; ft[4]=s01; ft[5]=s02;
  ft[6]=s01; ft[7]=s11-1.0f; ft[8]=s12;
  ft[9]=s02; ft[10]=s12; ft[11]=s22-1.0f;
  ft[12]=detF-1.0f; ft[13]=ld-1.0f; ft[14]=f00c-1.0f; ft[15]=logf(f00c)-1.0f;
#pragma unroll
  for (int k=0;k<9;k++) ft[16+k] = C[(size_t)i*9+k];
#pragma unroll
  for (int k=25;k<32;k++) ft[k] = 0.0f;
#pragma unroll
  for (int k=0;k<9;k++) g_R[(size_t)i*9+k] = x[k];
}

// ---------------- phase 1b: fold constant latent into layer-1 bias ----------------
__global__ void b1eff_kernel(const float* __restrict__ emb, const int* __restrict__ traj,
                             const float* __restrict__ W1, const float* __restrict__ b1){
  int n = threadIdx.x;           // 0..255
  int t = traj[0];
  float s = b1[n];
#pragma unroll 8
  for (int d=0; d<128; d++)
    s = fmaf(emb[t*128 + d], W1[(25+d)*256 + n], s);
  g_b1eff[n] = s;
}

// ---------------- phase 2: fused MLP (3xTF32 split mma) + epilogue ----------------
__global__ __launch_bounds__(256,1) void mlp_kernel(
    const float* __restrict__ F,
    const float* __restrict__ W1,
    const float* __restrict__ W2, const float* __restrict__ b2,
    const float* __restrict__ W3, const float* __restrict__ b3,
    const float* __restrict__ W4, const float* __restrict__ b4,
    const float* __restrict__ W5, const float* __restrict__ b5,
    float* __restrict__ out, int B)
{
  extern __shared__ float sm[];
  float* H  = sm;                    // [128][HSTR]
  float* WB = sm + 128*HSTR;         // 2 x [32][WSTR]
  float* SB = WB + 2*32*WSTR;        // [256] bias

  const int tid  = threadIdx.x;
  const int lane = tid & 31;
  const int w    = tid >> 5;
  const int qr   = lane >> 2;        // 0..7
  const int qc   = lane & 3;         // 0..3
  const int wm   = w & 1;            // 2 m-warps
  const int wn   = w >> 1;           // 4 n-warps
  const int mBase = wm*64;
  const int nBase = wn*64;
  const int row0  = blockIdx.x * 128;

  const uint32_t wbAddr = (uint32_t)__cvta_generic_to_shared(WB);

  // ---- load padded feats into H ----
  {
    int r    = tid >> 1;
    int half = (tid & 1) * 16;
    float4 v0,v1,v2,v3;
    if (row0 + r < B){
      const float4* src = (const float4*)(g_feats + (size_t)(row0 + r)*32 + half);
      v0=src[0]; v1=src[1]; v2=src[2]; v3=src[3];
    } else { v0=v1=v2=v3=make_float4(0,0,0,0); }
    float* dst = H + r*HSTR + half;
    *(float4*)(dst+0)=v0; *(float4*)(dst+4)=v1; *(float4*)(dst+8)=v2; *(float4*)(dst+12)=v3;
  }
  // ---- stage W1 (rows 0..24, zero-pad to 32) into WB buf0; bias ----
  {
#pragma unroll
    for (int i=0;i<8;i++){
      int id = tid + i*256;
      int r  = id >> 6;
      int c4 = (id & 63) << 2;
      float4 v = make_float4(0,0,0,0);
      if (r < 25) v = *(const float4*)(W1 + r*256 + c4);
      *(float4*)(WB + r*WSTR + c4) = v;
    }
    SB[tid] = g_b1eff[tid];
  }
  __syncthreads();

  float acc[4][8][4];

  auto zero_acc = [&](){
#pragma unroll
    for (int mf=0;mf<4;mf++)
#pragma unroll
      for (int nt=0;nt<8;nt++)
#pragma unroll
        for (int k=0;k<4;k++) acc[mf][nt][k]=0.0f;
  };

  auto compute_chunk = [&](const float* Wb, int kcol0){
#pragma unroll 1
    for (int kt=0; kt<4; kt++){
      int kc = kcol0 + kt*8;
      uint32_t Ah[4][4], Al[4][4];
#pragma unroll
      for (int mf=0; mf<4; mf++){
        const float* hp = H + (mBase + mf*16 + qr)*HSTR + kc + qc;
        float a0 = hp[0];
        float a1 = hp[8*HSTR];
        float a2 = hp[4];
        float a3 = hp[8*HSTR + 4];
        split2(a0, Ah[mf][0], Al[mf][0]);
        split2(a1, Ah[mf][1], Al[mf][1]);
        split2(a2, Ah[mf][2], Al[mf][2]);
        split2(a3, Ah[mf][3], Al[mf][3]);
      }
#pragma unroll
      for (int nt=0; nt<8; nt++){
        const float* wp = Wb + (kt*8 + qc)*WSTR + nBase + nt*8 + qr;
        float b0 = wp[0];
        float b1 = wp[4*WSTR];
        uint32_t bh0,bl0,bh1,bl1;
        split2(b0, bh0, bl0);
        split2(b1, bh1, bl1);
#pragma unroll
        for (int mf=0; mf<4; mf++){
          mma8(acc[mf][nt], Ah[mf][0],Ah[mf][1],Ah[mf][2],Ah[mf][3], bh0,bh1);
          mma8(acc[mf][nt], Al[mf][0],Al[mf][1],Al[mf][2],Al[mf][3], bh0,bh1);
          mma8(acc[mf][nt], Ah[mf][0],Ah[mf][1],Ah[mf][2],Ah[mf][3], bl0,bl1);
        }
      }
    }
  };

  auto epilogue_gelu = [&](){
#pragma unroll
    for (int mf=0;mf<4;mf++){
      int r0 = mBase + mf*16 + qr;
#pragma unroll
      for (int nt=0;nt<8;nt++){
        int c0 = nBase + nt*8 + 2*qc;
        float v0 = gelu_f(acc[mf][nt][0] + SB[c0]);
        float v1 = gelu_f(acc[mf][nt][1] + SB[c0+1]);
        float v2 = gelu_f(acc[mf][nt][2] + SB[c0]);
        float v3 = gelu_f(acc[mf][nt][3] + SB[c0+1]);
        *(float2*)(H + r0*HSTR + c0)      = make_float2(v0,v1);
        *(float2*)(H + (r0+8)*HSTR + c0)  = make_float2(v2,v3);
      }
    }
  };

  auto load_chunk = [&](const float* Wg, int c, int bufsel){
    uint32_t base = wbAddr + (uint32_t)bufsel*(32*WSTR*4);
#pragma unroll
    for (int i=0;i<8;i++){
      int id = tid + i*256;
      int r  = id >> 6;
      int c4 = (id & 63) << 2;
      cpa16(base + (uint32_t)(r*WSTR + c4)*4, Wg + (c*32 + r)*256 + c4);
    }
  };

  // ---- layer 1 (K=32) ----
  zero_acc();
  compute_chunk(WB, 0);
  __syncthreads();
  epilogue_gelu();
  __syncthreads();

  // ---- layers 2..4 (K=256, streamed, double-buffered) ----
#pragma unroll 1
  for (int L=0; L<3; L++){
    const float* Wg = (L==0)? W2 : (L==1)? W3 : W4;
    const float* bg = (L==0)? b2 : (L==1)? b3 : b4;
    SB[tid] = bg[tid];
    zero_acc();
    load_chunk(Wg, 0, 0);
    cpa_commit();
#pragma unroll 1
    for (int c=0;c<8;c++){
      if (c < 7){ load_chunk(Wg, c+1, (c+1)&1); cpa_commit(); }
      if (c < 7) asm volatile("cp.async.wait_group 1;\n" ::: "memory");
      else       asm volatile("cp.async.wait_group 0;\n" ::: "memory");
      __syncthreads();
      compute_chunk(WB + (c&1)*32*WSTR, c*32);
      __syncthreads();
    }
    epilogue_gelu();
    __syncthreads();
  }

  // ---- layer 5 (N=16 padded, K=256) ----
  {
#pragma unroll
    for (int i=0;i<16;i++){
      int id = tid + i*256;
      int r  = id >> 4;
      int cc = id & 15;
      WB[r*16 + cc] = (cc < 9) ? W5[r*9 + cc] : 0.0f;
    }
    if (tid < 16) SB[tid] = (tid < 9) ? b5[tid] : 0.0f;
  }
  __syncthreads();

  float a5[2][4];
#pragma unroll
  for (int nt=0;nt<2;nt++)
#pragma unroll
    for (int k=0;k<4;k++) a5[nt][k]=0.0f;

  const int r5 = w*16 + qr;   // 8 warps x m16 = 128 rows
#pragma unroll 1
  for (int kt=0; kt<32; kt++){
    const float* hp = H + r5*HSTR + kt*8 + qc;
    float a0 = hp[0];
    float a1 = hp[8*HSTR];
    float a2 = hp[4];
    float a3 = hp[8*HSTR + 4];
    uint32_t Ah[4], Al[4];
    split2(a0,Ah[0],Al[0]); split2(a1,Ah[1],Al[1]);
    split2(a2,Ah[2],Al[2]); split2(a3,Ah[3],Al[3]);
#pragma unroll
    for (int nt=0;nt<2;nt++){
      const float* wp = WB + (kt*8 + qc)*16 + nt*8 + qr;
      float b0 = wp[0];
      float b1 = wp[4*16];
      uint32_t bh0,bl0,bh1,bl1;
      split2(b0,bh0,bl0); split2(b1,bh1,bl1);
      mma8(a5[nt], Ah[0],Ah[1],Ah[2],Ah[3], bh0,bh1);
      mma8(a5[nt], Al[0],Al[1],Al[2],Al[3], bh0,bh1);
      mma8(a5[nt], Ah[0],Ah[1],Ah[2],Ah[3], bl0,bl1);
    }
  }
  __syncthreads();
  // stage out16 into H as [128][16]
  {
    int c0 = 2*qc;
#pragma unroll
    for (int nt=0;nt<2;nt++){
      H[r5*16     + nt*8 + c0]   = a5[nt][0] + SB[nt*8 + c0];
      H[r5*16     + nt*8 + c0+1] = a5[nt][1] + SB[nt*8 + c0+1];
      H[(r5+8)*16 + nt*8 + c0]   = a5[nt][2] + SB[nt*8 + c0];
      H[(r5+8)*16 + nt*8 + c0+1] = a5[nt][3] + SB[nt*8 + c0+1];
    }
  }
  __syncthreads();

  // ---- final epilogue: symmetrize, P = R*xs, cauchy = P*F^T ----
  if (tid < 128){
    int gi = row0 + tid;
    if (gi < B){
      float xv[9];
#pragma unroll
      for (int k=0;k<9;k++) xv[k] = H[tid*16 + k];
      float xs[9];
      xs[0]=xv[0]; xs[4]=xv[4]; xs[8]=xv[8];
      xs[1]=0.5f*(xv[1]+xv[3]); xs[3]=xs[1];
      xs[2]=0.5f*(xv[2]+xv[6]); xs[6]=xs[2];
      xs[5]=0.5f*(xv[5]+xv[7]); xs[7]=xs[5];
      float r[9], f[9];
#pragma unroll
      for (int k=0;k<9;k++){ r[k]=g_R[(size_t)gi*9+k]; f[k]=F[(size_t)gi*9+k]; }
      float P[9];
#pragma unroll
      for (int i2=0;i2<3;i2++)
#pragma unroll
        for (int j=0;j<3;j++)
          P[3*i2+j] = r[3*i2+0]*xs[j] + r[3*i2+1]*xs[3+j] + r[3*i2+2]*xs[6+j];
#pragma unroll
      for (int i2=0;i2<3;i2++)
#pragma unroll
        for (int j=0;j<3;j++)
          out[(size_t)gi*9 + 3*i2 + j] = P[3*i2+0]*f[3*j+0] + P[3*i2+1]*f[3*j+1] + P[3*i2+2]*f[3*j+2];
    }
  }
}

// ---------------- launch ----------------
extern "C" void kernel_launch(void* const* d_in, const int* in_sizes, int n_in,
                              void* d_out, int out_size){
  const float* F    = (const float*)d_in[0];
  const float* C    = (const float*)d_in[1];
  const float* emb  = (const float*)d_in[2];
  const int*   traj = (const int*)  d_in[3];
  const float* W1   = (const float*)d_in[4];
  const float* b1   = (const float*)d_in[5];
  const float* W2   = (const float*)d_in[6];
  const float* b2   = (const float*)d_in[7];
  const float* W3   = (const float*)d_in[8];
  const float* b3   = (const float*)d_in[9];
  const float* W4   = (const float*)d_in[10];
  const float* b4   = (const float*)d_in[11];
  const float* W5   = (const float*)d_in[12];
  const float* b5   = (const float*)d_in[13];

  int B = in_sizes[0] / 9;
  if (B > BCAP) B = BCAP;

  cudaFuncSetAttribute(mlp_kernel, cudaFuncAttributeMaxDynamicSharedMemorySize, SMEM_BYTES);

  prep_kernel<<<(B + 255)/256, 256>>>(F, C, B);
  b1eff_kernel<<<1, 256>>>(emb, traj, W1, b1);
  mlp_kernel<<<(B + 127)/128, 256, SMEM_BYTES>>>(F, W1, W2,b2, W3,b3, W4,b4, W5,b5,
                                                 (float*)d_out, B);
}

// round 4
// speedup vs baseline: 1.5057x; 1.5057x over previous
#include <cuda_runtime.h>
#include <cuda_fp16.h>
#include <cstdint>
#include <math.h>

#define BCAP 262144
#define SH 264            // H smem stride in halves (132 words -> 4*qr+qc bank bijection)
#define SW 40             // W chunk smem stride in halves (20 words -> 20*qr+qc bijection)
#define HH_OFF 0
#define HL_OFF (128*SH)               // 33792 halves
#define WB_OFF (2*128*SH)             // 67584 halves
#define WBUF_H 10240                  // 256*40 halves per buffer
#define SB_BYTE (WB_OFF*2 + 4*WBUF_H*2)   // 217088
#define SMEM_BYTES (SB_BYTE + 1024)       // 218112

__device__ float g_feats[(size_t)BCAP*32];
__device__ float g_R[(size_t)BCAP*9];
__device__ float g_b1eff[256];
// pre-split transposed weights: [W1t: 256n x 32k][W2..4t: 3 x 256 x 256][W5t: 16 x 256]
#define W1T_OFF 0
#define W24_OFF 8192
#define W5T_OFF 204800
#define WTOT    208896
__device__ __align__(16) __half g_Wh[WTOT];
__device__ __align__(16) __half g_Wl[WTOT];

// ---------------- helpers ----------------
__device__ __forceinline__ float gelu_f(float x){
  return 0.5f*x*(1.0f + erff(x*0.7071067811865476f));
}
__device__ __forceinline__ void mma16(float d[4], const uint32_t a[4], uint32_t b0, uint32_t b1){
  asm volatile("mma.sync.aligned.m16n8k16.row.col.f32.f16.f16.f32 "
               "{%0,%1,%2,%3},{%4,%5,%6,%7},{%8,%9},{%0,%1,%2,%3};\n"
               : "+f"(d[0]),"+f"(d[1]),"+f"(d[2]),"+f"(d[3])
               : "r"(a[0]),"r"(a[1]),"r"(a[2]),"r"(a[3]),"r"(b0),"r"(b1));
}
__device__ __forceinline__ uint32_t ld32s(const __half* p){ return *(const uint32_t*)p; }
__device__ __forceinline__ void split_store(float v0, float v1, __half* ph, __half* pl){
  __half2 h = __floats2half2_rn(v0, v1);
  float2 hb = __half22float2(h);
  __half2 l = __floats2half2_rn(v0 - hb.x, v1 - hb.y);
  *(__half2*)ph = h;
  *(__half2*)pl = l;
}
__device__ __forceinline__ void cpa16(uint32_t dst, const void* src){
  asm volatile("cp.async.cg.shared.global [%0], [%1], 16;\n" :: "r"(dst), "l"(src) : "memory");
}
__device__ __forceinline__ void cpa_commit(){ asm volatile("cp.async.commit_group;\n" ::: "memory"); }

// ---------------- phase 1: per-element features (polar + eigen) ----------------
__global__ void prep_kernel(const float* __restrict__ F, const float* __restrict__ C, int B){
  int i = blockIdx.x*blockDim.x + threadIdx.x;
  if (i >= B) return;
  float f[9];
#pragma unroll
  for (int k=0;k<9;k++) f[k] = F[(size_t)i*9+k];

  float x[9];
#pragma unroll
  for (int k=0;k<9;k++) x[k]=f[k];
#pragma unroll
  for (int it=0; it<5; it++){
    float c00 = x[4]*x[8]-x[5]*x[7];
    float c01 = x[5]*x[6]-x[3]*x[8];
    float c02 = x[3]*x[7]-x[4]*x[6];
    float c10 = x[2]*x[7]-x[1]*x[8];
    float c11 = x[0]*x[8]-x[2]*x[6];
    float c12 = x[1]*x[6]-x[0]*x[7];
    float c20 = x[1]*x[5]-x[2]*x[4];
    float c21 = x[2]*x[3]-x[0]*x[5];
    float c22 = x[0]*x[4]-x[1]*x[3];
    float det = x[0]*c00 + x[1]*c01 + x[2]*c02;
    float s = 0.5f/det;
    x[0]=0.5f*x[0]+s*c00; x[1]=0.5f*x[1]+s*c01; x[2]=0.5f*x[2]+s*c02;
    x[3]=0.5f*x[3]+s*c10; x[4]=0.5f*x[4]+s*c11; x[5]=0.5f*x[5]+s*c12;
    x[6]=0.5f*x[6]+s*c20; x[7]=0.5f*x[7]+s*c21; x[8]=0.5f*x[8]+s*c22;
  }

  float s00 = f[0]*f[0]+f[3]*f[3]+f[6]*f[6];
  float s11 = f[1]*f[1]+f[4]*f[4]+f[7]*f[7];
  float s22 = f[2]*f[2]+f[5]*f[5]+f[8]*f[8];
  float s01 = f[0]*f[1]+f[3]*f[4]+f[6]*f[7];
  float s02 = f[0]*f[2]+f[3]*f[5]+f[6]*f[8];
  float s12 = f[1]*f[2]+f[4]*f[5]+f[7]*f[8];

  float q  = (s00+s11+s22)*(1.0f/3.0f);
  float b00=s00-q, b11=s11-q, b22=s22-q;
  float p2 = (b00*b00+b11*b11+b22*b22 + 2.0f*(s01*s01+s02*s02+s12*s12))*(1.0f/6.0f);
  float p  = sqrtf(fmaxf(p2, 0.0f));
  float l1,l2,l3;
  if (p < 1e-10f){ l1=l2=l3=q; }
  else {
    float detB = b00*(b11*b22 - s12*s12) - s01*(s01*b22 - s12*s02) + s02*(s01*s12 - b11*s02);
    float r = detB/(2.0f*p*p*p);
    r = fminf(1.0f, fmaxf(-1.0f, r));
    float phi = acosf(r)*(1.0f/3.0f);
    l1 = q + 2.0f*p*cosf(phi);
    l3 = q + 2.0f*p*cosf(phi + 2.0943951023931953f);
    l2 = 3.0f*q - l1 - l3;
  }
  float sg1 = sqrtf(fmaxf(l1,0.0f));
  float sg2 = sqrtf(fmaxf(l2,0.0f));
  float sg3 = sqrtf(fmaxf(l3,0.0f));

  float detF = f[0]*(f[4]*f[8]-f[5]*f[7]) - f[1]*(f[3]*f[8]-f[5]*f[6]) + f[2]*(f[3]*f[7]-f[4]*f[6]);
  float ld   = logf(detF);
  float f00c = fmaxf(f[0], 1e-6f);

  float* ft = g_feats + (size_t)i*32;
  ft[0]=sg1-1.0f; ft[1]=sg2-1.0f; ft[2]=sg3-1.0f;
  ft[3]=s00-1.0f; ft[4]=s01; ft[5]=s02;
  ft[6]=s01; ft[7]=s11-1.0f; ft[8]=s12;
  ft[9]=s02; ft[10]=s12; ft[11]=s22-1.0f;
  ft[12]=detF-1.0f; ft[13]=ld-1.0f; ft[14]=f00c-1.0f; ft[15]=logf(f00c)-1.0f;
#pragma unroll
  for (int k=0;k<9;k++) ft[16+k] = C[(size_t)i*9+k];
#pragma unroll
  for (int k=25;k<32;k++) ft[k] = 0.0f;
#pragma unroll
  for (int k=0;k<9;k++) g_R[(size_t)i*9+k] = x[k];
}

// ---------------- phase 1b: fold constant latent into layer-1 bias ----------------
__global__ void b1eff_kernel(const float* __restrict__ emb, const int* __restrict__ traj,
                             const float* __restrict__ W1, const float* __restrict__ b1){
  int n = threadIdx.x;
  int t = traj[0];
  float s = b1[n];
#pragma unroll 8
  for (int d=0; d<128; d++)
    s = fmaf(emb[t*128 + d], W1[(25+d)*256 + n], s);
  g_b1eff[n] = s;
}

// ---------------- phase 1c: pre-split + transpose weights into fp16 hi/lo ----------------
__global__ void presplit_kernel(const float* __restrict__ W1, const float* __restrict__ W2,
                                const float* __restrict__ W3, const float* __restrict__ W4,
                                const float* __restrict__ W5){
  int i = blockIdx.x*blockDim.x + threadIdx.x;
  if (i >= WTOT) return;
  float v;
  if (i < W24_OFF){                       // W1t [256n][32k]
    int n = i >> 5, k = i & 31;
    v = (k < 25) ? W1[k*256 + n] : 0.0f;
  } else if (i < W5T_OFF){                // W2..4 [256n][256k]
    int j = i - W24_OFF;
    const float* W = (j < 65536) ? W2 : (j < 131072) ? W3 : W4;
    int r = j & 65535;
    int n = r >> 8, k = r & 255;
    v = W[k*256 + n];
  } else {                                // W5t [16n][256k]
    int j = i - W5T_OFF;
    int n = j >> 8, k = j & 255;
    v = (n < 9) ? W5[k*9 + n] : 0.0f;
  }
  __half h = __float2half_rn(v);
  g_Wh[i] = h;
  g_Wl[i] = __float2half_rn(v - __half2float(h));
}

// ---------------- phase 2: fused MLP (3xFP16 split, m16n8k16) ----------------
__global__ __launch_bounds__(256,1) void mlp_kernel(
    const float* __restrict__ F,
    const float* __restrict__ b2, const float* __restrict__ b3,
    const float* __restrict__ b4, const float* __restrict__ b5,
    float* __restrict__ out, int B)
{
  extern __shared__ __half smh[];
  __half* Hh = smh + HH_OFF;
  __half* Hl = smh + HL_OFF;
  __half* WB = smh + WB_OFF;                 // 4 buffers of 10240 halves: [buf][hl]
  float*  SB = (float*)((char*)smh + SB_BYTE);

  const int tid  = threadIdx.x;
  const int lane = tid & 31;
  const int w    = tid >> 5;
  const int qr   = lane >> 2;
  const int qc   = lane & 3;
  const int wm   = w & 1;
  const int wn   = w >> 1;
  const int mBase = wm*64;
  const int nBase = wn*64;
  const int row0  = blockIdx.x * 128;

  const uint32_t wbAddr = (uint32_t)__cvta_generic_to_shared(WB);

  // ---- feats -> Hh/Hl (fp16 split) ----
  {
    int r   = tid >> 1;
    int off = (tid & 1) * 16;
    float v[16];
    if (row0 + r < B){
      const float4* src = (const float4*)(g_feats + (size_t)(row0 + r)*32 + off);
#pragma unroll
      for (int j=0;j<4;j++){ float4 t = src[j]; v[4*j]=t.x; v[4*j+1]=t.y; v[4*j+2]=t.z; v[4*j+3]=t.w; }
    } else {
#pragma unroll
      for (int j=0;j<16;j++) v[j]=0.0f;
    }
    __half* ph = Hh + r*SH + off;
    __half* pl = Hl + r*SH + off;
#pragma unroll
    for (int j=0;j<8;j++) split_store(v[2*j], v[2*j+1], ph + 2*j, pl + 2*j);
  }
  SB[tid] = g_b1eff[tid];

  // ---- load W1t chunk (k=32) into buf0 ----
  {
#pragma unroll
    for (int i=0;i<4;i++){
      int id = tid + i*256;              // 0..1023
      int n = id >> 2, j = id & 3;
      uint32_t doff = (uint32_t)(n*SW + j*8)*2;
      cpa16(wbAddr + doff,           g_Wh + W1T_OFF + n*32 + j*8);
      cpa16(wbAddr + WBUF_H*2 + doff, g_Wl + W1T_OFF + n*32 + j*8);
    }
    cpa_commit();
    asm volatile("cp.async.wait_group 0;\n" ::: "memory");
  }
  __syncthreads();

  float acc[4][8][4];
  auto zero_acc = [&](){
#pragma unroll
    for (int mf=0;mf<4;mf++)
#pragma unroll
      for (int nt=0;nt<8;nt++)
#pragma unroll
        for (int k=0;k<4;k++) acc[mf][nt][k]=0.0f;
  };

  auto compute_k16 = [&](const __half* wth, const __half* wtl, int kcA, int kkW){
    uint32_t Ah[4][4], Al[4][4];
#pragma unroll
    for (int mf=0; mf<4; mf++){
      const __half* hp = Hh + (mBase + mf*16 + qr)*SH + kcA + 2*qc;
      const __half* lp = Hl + (mBase + mf*16 + qr)*SH + kcA + 2*qc;
      Ah[mf][0]=ld32s(hp);          Ah[mf][1]=ld32s(hp+8*SH);
      Ah[mf][2]=ld32s(hp+8);        Ah[mf][3]=ld32s(hp+8*SH+8);
      Al[mf][0]=ld32s(lp);          Al[mf][1]=ld32s(lp+8*SH);
      Al[mf][2]=ld32s(lp+8);        Al[mf][3]=ld32s(lp+8*SH+8);
    }
#pragma unroll
    for (int nt=0; nt<8; nt++){
      const __half* wp = wth + (nBase + nt*8 + qr)*SW + kkW + 2*qc;
      const __half* wq = wtl + (nBase + nt*8 + qr)*SW + kkW + 2*qc;
      uint32_t bh0=ld32s(wp), bh1=ld32s(wp+8);
      uint32_t bl0=ld32s(wq), bl1=ld32s(wq+8);
#pragma unroll
      for (int mf=0; mf<4; mf++){
        mma16(acc[mf][nt], Ah[mf], bh0, bh1);
        mma16(acc[mf][nt], Al[mf], bh0, bh1);
        mma16(acc[mf][nt], Ah[mf], bl0, bl1);
      }
    }
  };

  auto epilogue_gelu = [&](){
#pragma unroll
    for (int mf=0;mf<4;mf++){
      int r0 = mBase + mf*16 + qr;
#pragma unroll
      for (int nt=0;nt<8;nt++){
        int c0 = nBase + nt*8 + 2*qc;
        float v0 = gelu_f(acc[mf][nt][0] + SB[c0]);
        float v1 = gelu_f(acc[mf][nt][1] + SB[c0+1]);
        float v2 = gelu_f(acc[mf][nt][2] + SB[c0]);
        float v3 = gelu_f(acc[mf][nt][3] + SB[c0+1]);
        split_store(v0, v1, Hh + r0*SH + c0,     Hl + r0*SH + c0);
        split_store(v2, v3, Hh + (r0+8)*SH + c0, Hl + (r0+8)*SH + c0);
      }
    }
  };

  auto load_chunk = [&](int gBase, int c, int bufsel){
    uint32_t base = wbAddr + (uint32_t)bufsel*(2*WBUF_H*2);
#pragma unroll
    for (int i=0;i<4;i++){
      int id = tid + i*256;
      int n = id >> 2, j = id & 3;
      uint32_t doff = (uint32_t)(n*SW + j*8)*2;
      const __half* srcH = g_Wh + gBase + n*256 + c*32 + j*8;
      const __half* srcL = g_Wl + gBase + n*256 + c*32 + j*8;
      cpa16(base + doff,             srcH);
      cpa16(base + WBUF_H*2 + doff,  srcL);
    }
  };

  // ---- layer 1 (K=32) ----
  zero_acc();
  compute_k16(WB, WB + WBUF_H, 0, 0);
  compute_k16(WB, WB + WBUF_H, 16, 16);
  __syncthreads();
  epilogue_gelu();
  __syncthreads();

  // ---- layers 2..4 (K=256, streamed, double-buffered) ----
#pragma unroll 1
  for (int L=0; L<3; L++){
    const float* bg = (L==0)? b2 : (L==1)? b3 : b4;
    int gBase = W24_OFF + L*65536;
    SB[tid] = bg[tid];
    zero_acc();
    load_chunk(gBase, 0, 0);
    cpa_commit();
#pragma unroll 1
    for (int c=0;c<8;c++){
      if (c < 7){ load_chunk(gBase, c+1, (c+1)&1); cpa_commit();
                  asm volatile("cp.async.wait_group 1;\n" ::: "memory"); }
      else      { asm volatile("cp.async.wait_group 0;\n" ::: "memory"); }
      __syncthreads();
      const __half* wh = WB + (c&1)*2*WBUF_H;
      const __half* wl = wh + WBUF_H;
      compute_k16(wh, wl, c*32,      0);
      compute_k16(wh, wl, c*32 + 16, 16);
      __syncthreads();
    }
    epilogue_gelu();
    __syncthreads();
  }

  // ---- layer 5 (N=16 padded, K=256) ----
  if (tid < 16) SB[tid] = (tid < 9) ? b5[tid] : 0.0f;
  {
#pragma unroll
    for (int i=0;i<2;i++){
      int id = tid + i*256;               // 0..511
      int n = id >> 5, j = id & 31;
      uint32_t doff = (uint32_t)(n*SH + j*8)*2;
      cpa16(wbAddr + doff,          g_Wh + W5T_OFF + n*256 + j*8);
      cpa16(wbAddr + 8448 + doff,   g_Wl + W5T_OFF + n*256 + j*8);
    }
    cpa_commit();
    asm volatile("cp.async.wait_group 0;\n" ::: "memory");
  }
  __syncthreads();

  float a5[2][4];
#pragma unroll
  for (int nt=0;nt<2;nt++)
#pragma unroll
    for (int k=0;k<4;k++) a5[nt][k]=0.0f;

  const int r5 = w*16 + qr;
#pragma unroll 1
  for (int kt=0; kt<16; kt++){
    int kk = kt*16;
    const __half* hp = Hh + r5*SH + kk + 2*qc;
    const __half* lp = Hl + r5*SH + kk + 2*qc;
    uint32_t Ah[4], Al[4];
    Ah[0]=ld32s(hp);   Ah[1]=ld32s(hp+8*SH); Ah[2]=ld32s(hp+8); Ah[3]=ld32s(hp+8*SH+8);
    Al[0]=ld32s(lp);   Al[1]=ld32s(lp+8*SH); Al[2]=ld32s(lp+8); Al[3]=ld32s(lp+8*SH+8);
#pragma unroll
    for (int nt=0;nt<2;nt++){
      const __half* wp = WB + (nt*8+qr)*SH + kk + 2*qc;
      const __half* wq = WB + 4224 + (nt*8+qr)*SH + kk + 2*qc;
      uint32_t bh0=ld32s(wp), bh1=ld32s(wp+8);
      uint32_t bl0=ld32s(wq), bl1=ld32s(wq+8);
      mma16(a5[nt], Ah, bh0, bh1);
      mma16(a5[nt], Al, bh0, bh1);
      mma16(a5[nt], Ah, bl0, bl1);
    }
  }
  __syncthreads();

  // stage out16 into WB region as float [128][17]
  float* stage = (float*)WB;
  {
    int c0 = 2*qc;
#pragma unroll
    for (int nt=0;nt<2;nt++){
      stage[r5*17     + nt*8 + c0]   = a5[nt][0] + SB[nt*8 + c0];
      stage[r5*17     + nt*8 + c0+1] = a5[nt][1] + SB[nt*8 + c0+1];
      stage[(r5+8)*17 + nt*8 + c0]   = a5[nt][2] + SB[nt*8 + c0];
      stage[(r5+8)*17 + nt*8 + c0+1] = a5[nt][3] + SB[nt*8 + c0+1];
    }
  }
  __syncthreads();

  // ---- final epilogue: symmetrize, P = R*xs, cauchy = P*F^T ----
  if (tid < 128){
    int gi = row0 + tid;
    if (gi < B){
      float xv[9];
#pragma unroll
      for (int k=0;k<9;k++) xv[k] = stage[tid*17 + k];
      float xs[9];
      xs[0]=xv[0]; xs[4]=xv[4]; xs[8]=xv[8];
      xs[1]=0.5f*(xv[1]+xv[3]); xs[3]=xs[1];
      xs[2]=0.5f*(xv[2]+xv[6]); xs[6]=xs[2];
      xs[5]=0.5f*(xv[5]+xv[7]); xs[7]=xs[5];
      float r[9], f[9];
#pragma unroll
      for (int k=0;k<9;k++){ r[k]=g_R[(size_t)gi*9+k]; f[k]=F[(size_t)gi*9+k]; }
      float P[9];
#pragma unroll
      for (int i2=0;i2<3;i2++)
#pragma unroll
        for (int j=0;j<3;j++)
          P[3*i2+j] = r[3*i2+0]*xs[j] + r[3*i2+1]*xs[3+j] + r[3*i2+2]*xs[6+j];
#pragma unroll
      for (int i2=0;i2<3;i2++)
#pragma unroll
        for (int j=0;j<3;j++)
          out[(size_t)gi*9 + 3*i2 + j] = P[3*i2+0]*f[3*j+0] + P[3*i2+1]*f[3*j+1] + P[3*i2+2]*f[3*j+2];
    }
  }
}

// ---------------- launch ----------------
extern "C" void kernel_launch(void* const* d_in, const int* in_sizes, int n_in,
                              void* d_out, int out_size){
  const float* F    = (const float*)d_in[0];
  const float* C    = (const float*)d_in[1];
  const float* emb  = (const float*)d_in[2];
  const int*   traj = (const int*)  d_in[3];
  const float* W1   = (const float*)d_in[4];
  const float* b1   = (const float*)d_in[5];
  const float* W2   = (const float*)d_in[6];
  const float* b2   = (const float*)d_in[7];
  const float* W3   = (const float*)d_in[8];
  const float* b3   = (const float*)d_in[9];
  const float* W4   = (const float*)d_in[10];
  const float* b4   = (const float*)d_in[11];
  const float* W5   = (const float*)d_in[12];
  const float* b5   = (const float*)d_in[13];

  int B = in_sizes[0] / 9;
  if (B > BCAP) B = BCAP;

  cudaFuncSetAttribute(mlp_kernel, cudaFuncAttributeMaxDynamicSharedMemorySize, SMEM_BYTES);

  prep_kernel<<<(B + 255)/256, 256>>>(F, C, B);
  presplit_kernel<<<(WTOT + 255)/256, 256>>>(W1, W2, W3, W4, W5);
  b1eff_kernel<<<1, 256>>>(emb, traj, W1, b1);
  mlp_kernel<<<(B + 127)/128, 256, SMEM_BYTES>>>(F, b2, b3, b4, b5, (float*)d_out, B);
}

// round 5
// speedup vs baseline: 1.6500x; 1.0959x over previous
#include <cuda_runtime.h>
#include <cuda_fp16.h>
#include <cstdint>
#include <math.h>

#define BCAP 262144
#define SH 264            // H smem stride in halves (132 words -> 4*qr+qc bank bijection)
#define SW 40             // W chunk smem stride in halves (20 words -> 20*qr+qc bijection)
#define HH_OFF 0
#define HL_OFF (128*SH)               // 33792 halves
#define WB_OFF (2*128*SH)             // 67584 halves
#define WBUF_H 10240                  // 256*40 halves per buffer
#define SB_BYTE (WB_OFF*2 + 4*WBUF_H*2)   // 217088
#define SMEM_BYTES (SB_BYTE + 1024)       // 218112

__device__ float g_feats[(size_t)BCAP*32];
__device__ float g_R[(size_t)BCAP*9];
__device__ float g_b1eff[256];
// pre-split transposed weights: [W1t: 256n x 32k][W2..4t: 3 x 256 x 256][W5t: 16 x 256]
#define W1T_OFF 0
#define W24_OFF 8192
#define W5T_OFF 204800
#define WTOT    208896
__device__ __align__(16) __half g_Wh[WTOT];
__device__ __align__(16) __half g_Wl[WTOT];

// ---------------- helpers ----------------
__device__ __forceinline__ float gelu_f(float x){
  return 0.5f*x*(1.0f + erff(x*0.7071067811865476f));
}
__device__ __forceinline__ void mma16(float d[4], const uint32_t a[4], uint32_t b0, uint32_t b1){
  asm volatile("mma.sync.aligned.m16n8k16.row.col.f32.f16.f16.f32 "
               "{%0,%1,%2,%3},{%4,%5,%6,%7},{%8,%9},{%0,%1,%2,%3};\n"
               : "+f"(d[0]),"+f"(d[1]),"+f"(d[2]),"+f"(d[3])
               : "r"(a[0]),"r"(a[1]),"r"(a[2]),"r"(a[3]),"r"(b0),"r"(b1));
}
__device__ __forceinline__ uint32_t ld32s(const __half* p){ return *(const uint32_t*)p; }
__device__ __forceinline__ void split_store(float v0, float v1, __half* ph, __half* pl){
  __half2 h = __floats2half2_rn(v0, v1);
  float2 hb = __half22float2(h);
  __half2 l = __floats2half2_rn(v0 - hb.x, v1 - hb.y);
  *(__half2*)ph = h;
  *(__half2*)pl = l;
}
__device__ __forceinline__ void cpa16(uint32_t dst, const void* src){
  asm volatile("cp.async.cg.shared.global [%0], [%1], 16;\n" :: "r"(dst), "l"(src) : "memory");
}
__device__ __forceinline__ void cpa_commit(){ asm volatile("cp.async.commit_group;\n" ::: "memory"); }

// ---------------- phase 1: per-element features (polar + eigen) ----------------
__global__ void prep_kernel(const float* __restrict__ F, const float* __restrict__ C, int B){
  int i = blockIdx.x*blockDim.x + threadIdx.x;
  if (i >= B) return;
  float f[9];
#pragma unroll
  for (int k=0;k<9;k++) f[k] = F[(size_t)i*9+k];

  float x[9];
#pragma unroll
  for (int k=0;k<9;k++) x[k]=f[k];
#pragma unroll
  for (int it=0; it<5; it++){
    float c00 = x[4]*x[8]-x[5]*x[7];
    float c01 = x[5]*x[6]-x[3]*x[8];
    float c02 = x[3]*x[7]-x[4]*x[6];
    float c10 = x[2]*x[7]-x[1]*x[8];
    float c11 = x[0]*x[8]-x[2]*x[6];
    float c12 = x[1]*x[6]-x[0]*x[7];
    float c20 = x[1]*x[5]-x[2]*x[4];
    float c21 = x[2]*x[3]-x[0]*x[5];
    float c22 = x[0]*x[4]-x[1]*x[3];
    float det = x[0]*c00 + x[1]*c01 + x[2]*c02;
    float s = 0.5f/det;
    x[0]=0.5f*x[0]+s*c00; x[1]=0.5f*x[1]+s*c01; x[2]=0.5f*x[2]+s*c02;
    x[3]=0.5f*x[3]+s*c10; x[4]=0.5f*x[4]+s*c11; x[5]=0.5f*x[5]+s*c12;
    x[6]=0.5f*x[6]+s*c20; x[7]=0.5f*x[7]+s*c21; x[8]=0.5f*x[8]+s*c22;
  }

  float s00 = f[0]*f[0]+f[3]*f[3]+f[6]*f[6];
  float s11 = f[1]*f[1]+f[4]*f[4]+f[7]*f[7];
  float s22 = f[2]*f[2]+f[5]*f[5]+f[8]*f[8];
  float s01 = f[0]*f[1]+f[3]*f[4]+f[6]*f[7];
  float s02 = f[0]*f[2]+f[3]*f[5]+f[6]*f[8];
  float s12 = f[1]*f[2]+f[4]*f[5]+f[7]*f[8];

  float q  = (s00+s11+s22)*(1.0f/3.0f);
  float b00=s00-q, b11=s11-q, b22=s22-q;
  float p2 = (b00*b00+b11*b11+b22*b22 + 2.0f*(s01*s01+s02*s02+s12*s12))*(1.0f/6.0f);
  float p  = sqrtf(fmaxf(p2, 0.0f));
  float l1,l2,l3;
  if (p < 1e-10f){ l1=l2=l3=q; }
  else {
    float detB = b00*(b11*b22 - s12*s12) - s01*(s01*b22 - s12*s02) + s02*(s01*s12 - b11*s02);
    float r = detB/(2.0f*p*p*p);
    r = fminf(1.0f, fmaxf(-1.0f, r));
    float phi = acosf(r)*(1.0f/3.0f);
    l1 = q + 2.0f*p*cosf(phi);
    l3 = q + 2.0f*p*cosf(phi + 2.0943951023931953f);
    l2 = 3.0f*q - l1 - l3;
  }
  float sg1 = sqrtf(fmaxf(l1,0.0f));
  float sg2 = sqrtf(fmaxf(l2,0.0f));
  float sg3 = sqrtf(fmaxf(l3,0.0f));

  float detF = f[0]*(f[4]*f[8]-f[5]*f[7]) - f[1]*(f[3]*f[8]-f[5]*f[6]) + f[2]*(f[3]*f[7]-f[4]*f[6]);
  float ld   = logf(detF);
  float f00c = fmaxf(f[0], 1e-6f);

  float* ft = g_feats + (size_t)i*32;
  ft[0]=sg1-1.0f; ft[1]=sg2-1.0f; ft[2]=sg3-1.0f;
  ft[3]=s00-1.0f; ft[4]=s01; ft[5]=s02;
  ft[6]=s01; ft[7]=s11-1.0f; ft[8]=s12;
  ft[9]=s02; ft[10]=s12; ft[11]=s22-1.0f;
  ft[12]=detF-1.0f; ft[13]=ld-1.0f; ft[14]=f00c-1.0f; ft[15]=logf(f00c)-1.0f;
#pragma unroll
  for (int k=0;k<9;k++) ft[16+k] = C[(size_t)i*9+k];
#pragma unroll
  for (int k=25;k<32;k++) ft[k] = 0.0f;
#pragma unroll
  for (int k=0;k<9;k++) g_R[(size_t)i*9+k] = x[k];
}

// ---------------- phase 1b: fold constant latent into layer-1 bias ----------------
__global__ void b1eff_kernel(const float* __restrict__ emb, const int* __restrict__ traj,
                             const float* __restrict__ W1, const float* __restrict__ b1){
  int n = threadIdx.x;
  int t = traj[0];
  float s = b1[n];
#pragma unroll 8
  for (int d=0; d<128; d++)
    s = fmaf(emb[t*128 + d], W1[(25+d)*256 + n], s);
  g_b1eff[n] = s;
}

// ---------------- phase 1c: pre-split + transpose weights into fp16 hi/lo ----------------
__global__ void presplit_kernel(const float* __restrict__ W1, const float* __restrict__ W2,
                                const float* __restrict__ W3, const float* __restrict__ W4,
                                const float* __restrict__ W5){
  int i = blockIdx.x*blockDim.x + threadIdx.x;
  if (i >= WTOT) return;
  float v;
  if (i < W24_OFF){                       // W1t [256n][32k]
    int n = i >> 5, k = i & 31;
    v = (k < 25) ? W1[k*256 + n] : 0.0f;
  } else if (i < W5T_OFF){                // W2..4 [256n][256k]
    int j = i - W24_OFF;
    const float* W = (j < 65536) ? W2 : (j < 131072) ? W3 : W4;
    int r = j & 65535;
    int n = r >> 8, k = r & 255;
    v = W[k*256 + n];
  } else {                                // W5t [16n][256k]
    int j = i - W5T_OFF;
    int n = j >> 8, k = j & 255;
    v = (n < 9) ? W5[k*9 + n] : 0.0f;
  }
  __half h = __float2half_rn(v);
  g_Wh[i] = h;
  g_Wl[i] = __float2half_rn(v - __half2float(h));
}

// ---------------- phase 2: fused MLP (3xFP16 split, m16n8k16, 16 warps) ----------------
__global__ __launch_bounds__(512,1) void mlp_kernel(
    const float* __restrict__ F,
    const float* __restrict__ b2, const float* __restrict__ b3,
    const float* __restrict__ b4, const float* __restrict__ b5,
    float* __restrict__ out, int B)
{
  extern __shared__ __half smh[];
  __half* Hh = smh + HH_OFF;
  __half* Hl = smh + HL_OFF;
  __half* WB = smh + WB_OFF;                 // 4 buffers of 10240 halves: [buf][hl]
  float*  SB = (float*)((char*)smh + SB_BYTE);

  const int tid  = threadIdx.x;
  const int lane = tid & 31;
  const int w    = tid >> 5;                 // 0..15
  const int qr   = lane >> 2;
  const int qc   = lane & 3;
  const int wm   = w & 1;                    // 2 m-warps
  const int wn   = w >> 1;                   // 8 n-warps
  const int mBase = wm*64;
  const int nBase = wn*32;
  const int row0  = blockIdx.x * 128;

  const uint32_t wbAddr = (uint32_t)__cvta_generic_to_shared(WB);

  // ---- feats -> Hh/Hl (fp16 split) ----
  {
    int r   = tid >> 2;                // 0..127
    int off = (tid & 3) * 8;
    float v[8];
    if (row0 + r < B){
      const float4* src = (const float4*)(g_feats + (size_t)(row0 + r)*32 + off);
#pragma unroll
      for (int j=0;j<2;j++){ float4 t = src[j]; v[4*j]=t.x; v[4*j+1]=t.y; v[4*j+2]=t.z; v[4*j+3]=t.w; }
    } else {
#pragma unroll
      for (int j=0;j<8;j++) v[j]=0.0f;
    }
    __half* ph = Hh + r*SH + off;
    __half* pl = Hl + r*SH + off;
#pragma unroll
    for (int j=0;j<4;j++) split_store(v[2*j], v[2*j+1], ph + 2*j, pl + 2*j);
  }
  if (tid < 256) SB[tid] = g_b1eff[tid];

  // ---- load W1t chunk (k=32) into buf0 ----
  {
#pragma unroll
    for (int i=0;i<2;i++){
      int id = tid + i*512;              // 0..1023
      int n = id >> 2, j = id & 3;
      uint32_t doff = (uint32_t)(n*SW + j*8)*2;
      cpa16(wbAddr + doff,            g_Wh + W1T_OFF + n*32 + j*8);
      cpa16(wbAddr + WBUF_H*2 + doff, g_Wl + W1T_OFF + n*32 + j*8);
    }
    cpa_commit();
    asm volatile("cp.async.wait_group 0;\n" ::: "memory");
  }
  __syncthreads();

  float acc[4][4][4];
  auto zero_acc = [&](){
#pragma unroll
    for (int mf=0;mf<4;mf++)
#pragma unroll
      for (int nt=0;nt<4;nt++)
#pragma unroll
        for (int k=0;k<4;k++) acc[mf][nt][k]=0.0f;
  };

  auto compute_k16 = [&](const __half* wth, const __half* wtl, int kcA, int kkW){
    uint32_t Ah[4][4], Al[4][4];
#pragma unroll
    for (int mf=0; mf<4; mf++){
      const __half* hp = Hh + (mBase + mf*16 + qr)*SH + kcA + 2*qc;
      const __half* lp = Hl + (mBase + mf*16 + qr)*SH + kcA + 2*qc;
      Ah[mf][0]=ld32s(hp);          Ah[mf][1]=ld32s(hp+8*SH);
      Ah[mf][2]=ld32s(hp+8);        Ah[mf][3]=ld32s(hp+8*SH+8);
      Al[mf][0]=ld32s(lp);          Al[mf][1]=ld32s(lp+8*SH);
      Al[mf][2]=ld32s(lp+8);        Al[mf][3]=ld32s(lp+8*SH+8);
    }
#pragma unroll
    for (int nt=0; nt<4; nt++){
      const __half* wp = wth + (nBase + nt*8 + qr)*SW + kkW + 2*qc;
      const __half* wq = wtl + (nBase + nt*8 + qr)*SW + kkW + 2*qc;
      uint32_t bh0=ld32s(wp), bh1=ld32s(wp+8);
      uint32_t bl0=ld32s(wq), bl1=ld32s(wq+8);
#pragma unroll
      for (int mf=0; mf<4; mf++){
        mma16(acc[mf][nt], Ah[mf], bh0, bh1);
        mma16(acc[mf][nt], Al[mf], bh0, bh1);
        mma16(acc[mf][nt], Ah[mf], bl0, bl1);
      }
    }
  };

  auto epilogue_gelu = [&](){
#pragma unroll
    for (int mf=0;mf<4;mf++){
      int r0 = mBase + mf*16 + qr;
#pragma unroll
      for (int nt=0;nt<4;nt++){
        int c0 = nBase + nt*8 + 2*qc;
        float v0 = gelu_f(acc[mf][nt][0] + SB[c0]);
        float v1 = gelu_f(acc[mf][nt][1] + SB[c0+1]);
        float v2 = gelu_f(acc[mf][nt][2] + SB[c0]);
        float v3 = gelu_f(acc[mf][nt][3] + SB[c0+1]);
        split_store(v0, v1, Hh + r0*SH + c0,     Hl + r0*SH + c0);
        split_store(v2, v3, Hh + (r0+8)*SH + c0, Hl + (r0+8)*SH + c0);
      }
    }
  };

  auto load_chunk = [&](int gBase, int c, int bufsel){
    uint32_t base = wbAddr + (uint32_t)bufsel*(2*WBUF_H*2);
#pragma unroll
    for (int i=0;i<2;i++){
      int id = tid + i*512;
      int n = id >> 2, j = id & 3;
      uint32_t doff = (uint32_t)(n*SW + j*8)*2;
      const __half* srcH = g_Wh + gBase + n*256 + c*32 + j*8;
      const __half* srcL = g_Wl + gBase + n*256 + c*32 + j*8;
      cpa16(base + doff,            srcH);
      cpa16(base + WBUF_H*2 + doff, srcL);
    }
  };

  // ---- layer 1 (K=32) ----
  zero_acc();
  compute_k16(WB, WB + WBUF_H, 0, 0);
  compute_k16(WB, WB + WBUF_H, 16, 16);
  __syncthreads();
  epilogue_gelu();
  __syncthreads();

  // ---- layers 2..4 (K=256, streamed, double-buffered) ----
#pragma unroll 1
  for (int L=0; L<3; L++){
    const float* bg = (L==0)? b2 : (L==1)? b3 : b4;
    int gBase = W24_OFF + L*65536;
    if (tid < 256) SB[tid] = bg[tid];
    zero_acc();
    load_chunk(gBase, 0, 0);
    cpa_commit();
#pragma unroll 1
    for (int c=0;c<8;c++){
      if (c < 7){ load_chunk(gBase, c+1, (c+1)&1); cpa_commit();
                  asm volatile("cp.async.wait_group 1;\n" ::: "memory"); }
      else      { asm volatile("cp.async.wait_group 0;\n" ::: "memory"); }
      __syncthreads();
      const __half* wh = WB + (c&1)*2*WBUF_H;
      const __half* wl = wh + WBUF_H;
      compute_k16(wh, wl, c*32,      0);
      compute_k16(wh, wl, c*32 + 16, 16);
      __syncthreads();
    }
    epilogue_gelu();
    __syncthreads();
  }

  // ---- layer 5 (N=16 padded, K=256) ----
  if (tid < 16) SB[tid] = (tid < 9) ? b5[tid] : 0.0f;
  {
    int id = tid;                         // 0..511
    int n = id >> 5, j = id & 31;
    uint32_t doff = (uint32_t)(n*SH + j*8)*2;
    cpa16(wbAddr + doff,          g_Wh + W5T_OFF + n*256 + j*8);
    cpa16(wbAddr + 8448 + doff,   g_Wl + W5T_OFF + n*256 + j*8);
    cpa_commit();
    asm volatile("cp.async.wait_group 0;\n" ::: "memory");
  }
  __syncthreads();

  float* stage = (float*)WB;    // reused after L5 weights consumed; sync below guards
  if (w < 8){
    float a5[2][4];
#pragma unroll
    for (int nt=0;nt<2;nt++)
#pragma unroll
      for (int k=0;k<4;k++) a5[nt][k]=0.0f;

    const int r5 = w*16 + qr;
#pragma unroll 1
    for (int kt=0; kt<16; kt++){
      int kk = kt*16;
      const __half* hp = Hh + r5*SH + kk + 2*qc;
      const __half* lp = Hl + r5*SH + kk + 2*qc;
      uint32_t Ah[4], Al[4];
      Ah[0]=ld32s(hp);   Ah[1]=ld32s(hp+8*SH); Ah[2]=ld32s(hp+8); Ah[3]=ld32s(hp+8*SH+8);
      Al[0]=ld32s(lp);   Al[1]=ld32s(lp+8*SH); Al[2]=ld32s(lp+8); Al[3]=ld32s(lp+8*SH+8);
#pragma unroll
      for (int nt=0;nt<2;nt++){
        const __half* wp = WB + (nt*8+qr)*SH + kk + 2*qc;
        const __half* wq = WB + 4224 + (nt*8+qr)*SH + kk + 2*qc;
        uint32_t bh0=ld32s(wp), bh1=ld32s(wp+8);
        uint32_t bl0=ld32s(wq), bl1=ld32s(wq+8);
        mma16(a5[nt], Ah, bh0, bh1);
        mma16(a5[nt], Al, bh0, bh1);
        mma16(a5[nt], Ah, bl0, bl1);
      }
    }
    __syncthreads();   // all L5 weight reads done before stage overwrite
    {
      int c0 = 2*qc;
#pragma unroll
      for (int nt=0;nt<2;nt++){
        stage[r5*17     + nt*8 + c0]   = a5[nt][0] + SB[nt*8 + c0];
        stage[r5*17     + nt*8 + c0+1] = a5[nt][1] + SB[nt*8 + c0+1];
        stage[(r5+8)*17 + nt*8 + c0]   = a5[nt][2] + SB[nt*8 + c0];
        stage[(r5+8)*17 + nt*8 + c0+1] = a5[nt][3] + SB[nt*8 + c0+1];
      }
    }
  } else {
    __syncthreads();   // matching barrier for idle warps
  }
  __syncthreads();

  // ---- final epilogue: symmetrize, P = R*xs, cauchy = P*F^T ----
  if (tid < 128){
    int gi = row0 + tid;
    if (gi < B){
      float xv[9];
#pragma unroll
      for (int k=0;k<9;k++) xv[k] = stage[tid*17 + k];
      float xs[9];
      xs[0]=xv[0]; xs[4]=xv[4]; xs[8]=xv[8];
      xs[1]=0.5f*(xv[1]+xv[3]); xs[3]=xs[1];
      xs[2]=0.5f*(xv[2]+xv[6]); xs[6]=xs[2];
      xs[5]=0.5f*(xv[5]+xv[7]); xs[7]=xs[5];
      float r[9], f[9];
#pragma unroll
      for (int k=0;k<9;k++){ r[k]=g_R[(size_t)gi*9+k]; f[k]=F[(size_t)gi*9+k]; }
      float P[9];
#pragma unroll
      for (int i2=0;i2<3;i2++)
#pragma unroll
        for (int j=0;j<3;j++)
          P[3*i2+j] = r[3*i2+0]*xs[j] + r[3*i2+1]*xs[3+j] + r[3*i2+2]*xs[6+j];
#pragma unroll
      for (int i2=0;i2<3;i2++)
#pragma unroll
        for (int j=0;j<3;j++)
          out[(size_t)gi*9 + 3*i2 + j] = P[3*i2+0]*f[3*j+0] + P[3*i2+1]*f[3*j+1] + P[3*i2+2]*f[3*j+2];
    }
  }
}

// ---------------- launch ----------------
extern "C" void kernel_launch(void* const* d_in, const int* in_sizes, int n_in,
                              void* d_out, int out_size){
  const float* F    = (const float*)d_in[0];
  const float* C    = (const float*)d_in[1];
  const float* emb  = (const float*)d_in[2];
  const int*   traj = (const int*)  d_in[3];
  const float* W1   = (const float*)d_in[4];
  const float* b1   = (const float*)d_in[5];
  const float* W2   = (const float*)d_in[6];
  const float* b2   = (const float*)d_in[7];
  const float* W3   = (const float*)d_in[8];
  const float* b3   = (const float*)d_in[9];
  const float* W4   = (const float*)d_in[10];
  const float* b4   = (const float*)d_in[11];
  const float* W5   = (const float*)d_in[12];
  const float* b5   = (const float*)d_in[13];

  int B = in_sizes[0] / 9;
  if (B > BCAP) B = BCAP;

  cudaFuncSetAttribute(mlp_kernel, cudaFuncAttributeMaxDynamicSharedMemorySize, SMEM_BYTES);

  prep_kernel<<<(B + 255)/256, 256>>>(F, C, B);
  presplit_kernel<<<(WTOT + 255)/256, 256>>>(W1, W2, W3, W4, W5);
  b1eff_kernel<<<1, 256>>>(emb, traj, W1, b1);
  mlp_kernel<<<(B + 127)/128, 512, SMEM_BYTES>>>(F, b2, b3, b4, b5, (float*)d_out, B);
}